// round 6
// baseline (speedup 1.0000x reference)
#include <cuda_runtime.h>
#include <cuda_bf16.h>
#include <mma.h>
#include <cstdint>
#include <math.h>

using namespace nvcuda;

#define N_NODES 50000
#define N_EDGES 800000
#define MULC 32
#define RADC 8
#define FCC 64

#define INV_SQRT_MUL 0.17677669529663687f
#define INV_SQRT_RAD 0.35355339059327373f
#define INV_SQRT_FC  0.125f
#define INV_SQRT_NN  0.25f
#define INV_SQRT_2MUL 0.125f
#define INV_SQRT3_C 0.5773502691896258f
#define MIX_C 0.9238795325112867f
#define MIX_S 0.3826834323650898f

typedef unsigned long long u64;
typedef unsigned int u32;

// ---------------- f32x2 helpers (out_kernel) ---------------------------------
__device__ __forceinline__ u64 pack2(float lo, float hi) {
    u64 d; asm("mov.b64 %0, {%1, %2};" : "=l"(d) : "f"(lo), "f"(hi)); return d;
}
__device__ __forceinline__ float2 unpack2(u64 v) {
    float lo, hi; asm("mov.b64 {%0, %1}, %2;" : "=f"(lo), "=f"(hi) : "l"(v));
    return make_float2(lo, hi);
}
__device__ __forceinline__ u64 fma2(u64 a, u64 b, u64 c) {
    u64 d; asm("fma.rn.f32x2 %0, %1, %2, %3;" : "=l"(d) : "l"(a), "l"(b), "l"(c));
    return d;
}
__device__ __forceinline__ u64 ld2(const float2* p) {
    float2 v = *p;
    u64 d; asm("mov.b64 %0, {%1, %2};" : "=l"(d) : "f"(v.x), "f"(v.y)); return d;
}

// gelu(x) = x * sigmoid(2u),  u = 0.79788456(x + 0.044715 x^3)
__device__ __forceinline__ float gelu_fast(float x) {
    float x2 = x * x;
    float arg = x * (-1.5957691216057308f - 0.07135481627352344f * x2); // -2u
    float p = __expf(arg);
    return __fdividef(x, 1.0f + p);
}

// pack (lo_arg, hi_arg) as bf16x2: element0 (low 16 bits) = lo_val
__device__ __forceinline__ unsigned cvt_bf16x2(float hi_val, float lo_val) {
    unsigned r; asm("cvt.rn.bf16x2.f32 %0, %1, %2;" : "=r"(r) : "f"(hi_val), "f"(lo_val));
    return r;
}

// ---------------- scratch ----------------------------------------------------
__device__ __align__(16) float g_f0[N_NODES * MULC];
__device__ __align__(16) float g_f1[N_NODES * 3 * MULC];
__device__ __align__(16) float g_self0[N_NODES * MULC];
__device__ __align__(16) float g_self1[N_NODES * 3 * MULC];
__device__ __align__(16) float g_n0[N_NODES * 2 * MULC];
__device__ __align__(16) float g_n1[N_NODES * 3 * 2 * MULC];
__device__ int g_cnt[N_NODES];
__device__ int g_off[N_NODES];
__device__ int g_perm[N_EDGES];

// ---------------- kernel 1: node pre-transforms + zeroing --------------------
#define PRE_BLOCKS 6250
#define ZERO_BLOCKS 1088
__global__ void node_pre_kernel(const float* __restrict__ node_s,
                                const float* __restrict__ node_v,
                                const float* __restrict__ Wf0,
                                const float* __restrict__ Ws0,
                                const float* __restrict__ Wf1,
                                const float* __restrict__ Ws1) {
    if (blockIdx.x >= PRE_BLOCKS) {
        int i = (blockIdx.x - PRE_BLOCKS) * blockDim.x + threadIdx.x;
        int stride = ZERO_BLOCKS * blockDim.x;
        float4* p0 = (float4*)g_n0;
        float4* p1 = (float4*)g_n1;
        const float4 z = make_float4(0.f, 0.f, 0.f, 0.f);
        for (int k = i; k < N_NODES * 16; k += stride) p0[k] = z;
        for (int k = i; k < N_NODES * 48; k += stride) p1[k] = z;
        for (int k = i; k < N_NODES; k += stride) g_cnt[k] = 0;
        return;
    }

    __shared__ float sWf0[1024], sWs0[1024], sWf1[1024], sWs1[1024];
    for (int i = threadIdx.x; i < 1024; i += blockDim.x) {
        sWf0[i] = Wf0[i] * INV_SQRT_MUL;
        sWs0[i] = Ws0[i] * (INV_SQRT_MUL * MIX_C);
        sWf1[i] = Wf1[i] * INV_SQRT_MUL;
        sWs1[i] = Ws1[i] * (INV_SQRT_MUL * MIX_C);
    }
    __syncthreads();

    int lane = threadIdx.x & 31;
    int warp = threadIdx.x >> 5;
    int n = blockIdx.x * (blockDim.x >> 5) + warp;
    if (n >= N_NODES) return;

    float sv  = node_s[n * 32 + lane];
    float vx  = node_v[n * 96 + lane * 3 + 0];
    float vy  = node_v[n * 96 + lane * 3 + 1];
    float vz  = node_v[n * 96 + lane * 3 + 2];

    float f0 = 0.f, s0 = 0.f;
    float f1x = 0.f, f1y = 0.f, f1z = 0.f;
    float s1x = 0.f, s1y = 0.f, s1z = 0.f;

    #pragma unroll 8
    for (int u = 0; u < 32; u++) {
        float su = __shfl_sync(0xffffffffu, sv, u);
        float ux = __shfl_sync(0xffffffffu, vx, u);
        float uy = __shfl_sync(0xffffffffu, vy, u);
        float uz = __shfl_sync(0xffffffffu, vz, u);
        float wf0 = sWf0[u * 32 + lane];
        float ws0 = sWs0[u * 32 + lane];
        float wf1 = sWf1[u * 32 + lane];
        float ws1 = sWs1[u * 32 + lane];
        f0 += su * wf0;  s0 += su * ws0;
        f1x += ux * wf1; f1y += uy * wf1; f1z += uz * wf1;
        s1x += ux * ws1; s1y += uy * ws1; s1z += uz * ws1;
    }

    g_f0[n * 32 + lane] = f0;
    g_self0[n * 32 + lane] = s0;
    g_f1[n * 96 + 0 * 32 + lane] = f1x;
    g_f1[n * 96 + 1 * 32 + lane] = f1y;
    g_f1[n * 96 + 2 * 32 + lane] = f1z;
    g_self1[n * 96 + 0 * 32 + lane] = s1x;
    g_self1[n * 96 + 1 * 32 + lane] = s1y;
    g_self1[n * 96 + 2 * 32 + lane] = s1z;
}

// ---------------- sort kernels ------------------------------------------------
__global__ void hist_kernel(const int* __restrict__ edge_dst) {
    int i = blockIdx.x * blockDim.x + threadIdx.x;
    if (i < N_EDGES) atomicAdd(&g_cnt[edge_dst[i]], 1);
}

__global__ void scan_kernel() {
    __shared__ int wsum[32];
    __shared__ int s_carry;
    const int tid = threadIdx.x;
    const int lane = tid & 31, wp = tid >> 5;
    if (tid == 0) s_carry = 0;
    __syncthreads();
    for (int b = 0; b < N_NODES; b += 1024) {
        int i = b + tid;
        int v = (i < N_NODES) ? g_cnt[i] : 0;
        int s = v;
        #pragma unroll
        for (int o = 1; o < 32; o <<= 1) {
            int t = __shfl_up_sync(0xffffffffu, s, o);
            if (lane >= o) s += t;
        }
        if (lane == 31) wsum[wp] = s;
        __syncthreads();
        if (wp == 0) {
            int ws = wsum[lane];
            #pragma unroll
            for (int o = 1; o < 32; o <<= 1) {
                int t = __shfl_up_sync(0xffffffffu, ws, o);
                if (lane >= o) ws += t;
            }
            wsum[lane] = ws;
        }
        __syncthreads();
        int carry = s_carry;
        int excl = carry + (wp > 0 ? wsum[wp - 1] : 0) + s - v;
        if (i < N_NODES) g_off[i] = excl;
        __syncthreads();
        if (tid == 1023) s_carry = excl + v;
        __syncthreads();
    }
}

__global__ void scatter_kernel(const int* __restrict__ edge_dst) {
    int i = blockIdx.x * blockDim.x + threadIdx.x;
    if (i < N_EDGES) {
        int d = edge_dst[i];
        int pos = atomicAdd(&g_off[d], 1);
        g_perm[pos] = i;
    }
}

// ---------------- kernel 2: edge phase (wmma bf16 hi/lo, dst-sorted) ---------
#define EDGE_WARPS 14
#define NTILES (N_EDGES / 16)    /* 50000 */

// element strides
#define A0S 24     /* bf16 */
#define AS  72     /* bf16 */
#define CS  76     /* f32  */
#define B0S 72
#define W1S 72
#define WPS 136

// smem byte offsets
#define OFF_B0H 0
#define OFF_B0L (OFF_B0H + 16 * B0S * 2)          /* 2304 */
#define OFF_W1H (OFF_B0L + 16 * B0S * 2)          /* 4608 */
#define OFF_W1L (OFF_W1H + 64 * W1S * 2)          /* 13824 */
#define OFF_WPH (OFF_W1L + 64 * W1S * 2)          /* 23040 */
#define OFF_WPL (OFF_WPH + 64 * WPS * 2)          /* 40448 */
#define OFF_PW  (OFF_WPL + 64 * WPS * 2)          /* 57856 */
#define PW_A0H  0
#define PW_A0L  (PW_A0H + 16 * A0S * 2)           /* 768 */
#define PW_AHI  (PW_A0L + 16 * A0S * 2)           /* 1536 */
#define PW_ALO  (PW_AHI + 16 * AS * 2)            /* 3840 */
#define PW_C    (PW_ALO + 16 * AS * 2)            /* 6144 */
#define PW_META (PW_C + 16 * CS * 4)              /* 11008 */
#define PW_SIZE 11520
#define EDGE_SMEM_BYTES (OFF_PW + EDGE_WARPS * PW_SIZE)   /* 219136 */

// gelu + bf16 hi/lo split: Cb[16][CS] f32 -> hi/lo bf16 [16][AS]
__device__ __forceinline__ void gelu_split_epilogue(const float* Cb,
                                                    __nv_bfloat16* hi,
                                                    __nv_bfloat16* lo,
                                                    int lane) {
    int r = lane >> 1, h = lane & 1;
    const float* row = Cb + r * CS + h * 32;
    unsigned* hrow = (unsigned*)(hi + r * AS + h * 32);
    unsigned* lrow = (unsigned*)(lo + r * AS + h * 32);
    #pragma unroll
    for (int cp = 0; cp < 16; cp++) {
        float2 v = *(const float2*)(row + 2 * cp);
        float g0 = gelu_fast(v.x);
        float g1 = gelu_fast(v.y);
        unsigned hp = cvt_bf16x2(g1, g0);
        float h0 = __uint_as_float(hp << 16);
        float h1 = __uint_as_float(hp & 0xffff0000u);
        unsigned lp = cvt_bf16x2(g1 - h1, g0 - h0);
        hrow[cp] = hp;
        lrow[cp] = lp;
    }
}

__global__ __launch_bounds__(EDGE_WARPS * 32, 1)
void edge_kernel(const float* __restrict__ sh0,
                 const float* __restrict__ sh1,
                 const float* __restrict__ edge_scalar,
                 const int* __restrict__ edge_src,
                 const int* __restrict__ edge_dst,
                 const float* __restrict__ mlp_w0,
                 const float* __restrict__ mlp_w1,
                 const float* __restrict__ wp0,
                 const float* __restrict__ wp1,
                 const float* __restrict__ wp2,
                 const float* __restrict__ wp3) {
    extern __shared__ char sm[];
    const int tid  = threadIdx.x;
    const int lane = tid & 31;
    const int wid  = tid >> 5;

    __nv_bfloat16* sB0h = (__nv_bfloat16*)(sm + OFF_B0H);
    __nv_bfloat16* sB0l = (__nv_bfloat16*)(sm + OFF_B0L);
    __nv_bfloat16* sW1h = (__nv_bfloat16*)(sm + OFF_W1H);
    __nv_bfloat16* sW1l = (__nv_bfloat16*)(sm + OFF_W1L);
    __nv_bfloat16* sWPh = (__nv_bfloat16*)(sm + OFF_WPH);
    __nv_bfloat16* sWPl = (__nv_bfloat16*)(sm + OFF_WPL);

    // ---- weight prep (hi/lo bf16 split, scales folded) -----------------------
    for (int i = tid; i < 16 * 64; i += blockDim.x) {
        int k = i >> 6, n = i & 63;
        float x = (k < 8) ? mlp_w0[k * 64 + n] * INV_SQRT_RAD : 0.0f;
        __nv_bfloat16 h = __float2bfloat16_rn(x);
        __nv_bfloat16 l = __float2bfloat16_rn(x - __bfloat162float(h));
        sB0h[k * B0S + n] = h;
        sB0l[k * B0S + n] = l;
    }
    for (int i = tid; i < 64 * 64; i += blockDim.x) {
        int k = i >> 6, n = i & 63;
        float x = mlp_w1[k * 64 + n] * INV_SQRT_FC;
        __nv_bfloat16 h = __float2bfloat16_rn(x);
        __nv_bfloat16 l = __float2bfloat16_rn(x - __bfloat162float(h));
        sW1h[k * W1S + n] = h;
        sW1l[k * W1S + n] = l;
    }
    const float wpsc = INV_SQRT_FC * INV_SQRT_NN;
    for (int i = tid; i < 64 * 128; i += blockDim.x) {
        int k = i >> 7, n = i & 127;
        int p = n >> 5, c = n & 31;
        const float* wpp = (p == 0) ? wp0 : (p == 1) ? wp1 : (p == 2) ? wp2 : wp3;
        float sc = (p == 3) ? wpsc * INV_SQRT3_C : wpsc;
        float x = wpp[k * 32 + c] * sc;
        __nv_bfloat16 h = __float2bfloat16_rn(x);
        __nv_bfloat16 l = __float2bfloat16_rn(x - __bfloat162float(h));
        sWPh[k * WPS + n] = h;
        sWPl[k * WPS + n] = l;
    }
    // zero a0 cols 8..15 for every warp (once)
    for (int i = tid; i < EDGE_WARPS * 16 * 8; i += blockDim.x) {
        int w = i >> 7;
        int r = (i >> 3) & 15;
        int c = 8 + (i & 7);
        char* pw = sm + OFF_PW + w * PW_SIZE;
        ((__nv_bfloat16*)(pw + PW_A0H))[r * A0S + c] = __float2bfloat16_rn(0.0f);
        ((__nv_bfloat16*)(pw + PW_A0L))[r * A0S + c] = __float2bfloat16_rn(0.0f);
    }
    __syncthreads();

    char* pw = sm + OFF_PW + wid * PW_SIZE;
    __nv_bfloat16* a0h = (__nv_bfloat16*)(pw + PW_A0H);
    __nv_bfloat16* a0l = (__nv_bfloat16*)(pw + PW_A0L);
    __nv_bfloat16* aHi = (__nv_bfloat16*)(pw + PW_AHI);
    __nv_bfloat16* aLo = (__nv_bfloat16*)(pw + PW_ALO);
    float* Cb   = (float*)(pw + PW_C);
    int*   mpid = (int*)(pw + PW_META);
    int*   msrc = mpid + 16;
    int*   mdst = msrc + 16;
    float* msh0 = (float*)(mdst + 16);
    float* msh1 = msh0 + 16;

    typedef wmma::fragment<wmma::matrix_a, 16, 16, 16, __nv_bfloat16, wmma::row_major> FragA;
    typedef wmma::fragment<wmma::matrix_b, 16, 16, 16, __nv_bfloat16, wmma::row_major> FragB;
    typedef wmma::fragment<wmma::accumulator, 16, 16, 16, float> FragC;

    for (int t = blockIdx.x * EDGE_WARPS + wid; t < NTILES; t += gridDim.x * EDGE_WARPS) {
        const int base = t * 16;

        // ---- stage meta via permutation (dst-sorted order) ---------------------
        if (lane < 16) {
            int pid = g_perm[base + lane];
            mpid[lane] = pid;
            msrc[lane] = edge_src[pid];
            mdst[lane] = edge_dst[pid];
            msh0[lane] = sh0[pid];
        }
        __syncwarp();
        #pragma unroll
        for (int j = lane; j < 48; j += 32) {
            int e = j / 3;
            msh1[j] = sh1[mpid[e] * 3 + (j - e * 3)];
        }
        {
            int e = lane >> 1, kh = lane & 1;
            int pid = mpid[e];
            float4 es = __ldg((const float4*)(edge_scalar + (size_t)pid * 8 + kh * 4));
            unsigned hp0 = cvt_bf16x2(es.y, es.x);
            unsigned lp0 = cvt_bf16x2(es.y - __uint_as_float(hp0 & 0xffff0000u),
                                      es.x - __uint_as_float(hp0 << 16));
            unsigned hp1 = cvt_bf16x2(es.w, es.z);
            unsigned lp1 = cvt_bf16x2(es.w - __uint_as_float(hp1 & 0xffff0000u),
                                      es.z - __uint_as_float(hp1 << 16));
            unsigned* dh = (unsigned*)(a0h + e * A0S + kh * 4);
            unsigned* dl = (unsigned*)(a0l + e * A0S + kh * 4);
            dh[0] = hp0; dh[1] = hp1;
            dl[0] = lp0; dl[1] = lp1;
        }
        __syncwarp();

        // ---- GEMM0: C[16,64] = a0 @ B0 ----------------------------------------
        {
            FragA fah, fal;
            wmma::load_matrix_sync(fah, a0h, A0S);
            wmma::load_matrix_sync(fal, a0l, A0S);
            #pragma unroll
            for (int j = 0; j < 4; j++) {
                FragC acc;
                wmma::fill_fragment(acc, 0.0f);
                FragB fbh, fbl;
                wmma::load_matrix_sync(fbh, sB0h + j * 16, B0S);
                wmma::load_matrix_sync(fbl, sB0l + j * 16, B0S);
                wmma::mma_sync(acc, fah, fbh, acc);
                wmma::mma_sync(acc, fah, fbl, acc);
                wmma::mma_sync(acc, fal, fbh, acc);
                wmma::store_matrix_sync(Cb + j * 16, acc, CS, wmma::mem_row_major);
            }
        }
        __syncwarp();
        gelu_split_epilogue(Cb, aHi, aLo, lane);
        __syncwarp();

        // ---- GEMM1: C[16,64] = h0 @ W1 ----------------------------------------
        {
            FragA fah[4], fal[4];
            #pragma unroll
            for (int kt = 0; kt < 4; kt++) {
                wmma::load_matrix_sync(fah[kt], aHi + kt * 16, AS);
                wmma::load_matrix_sync(fal[kt], aLo + kt * 16, AS);
            }
            #pragma unroll
            for (int j = 0; j < 4; j++) {
                FragC acc;
                wmma::fill_fragment(acc, 0.0f);
                #pragma unroll
                for (int kt = 0; kt < 4; kt++) {
                    FragB fbh, fbl;
                    wmma::load_matrix_sync(fbh, sW1h + kt * 16 * W1S + j * 16, W1S);
                    wmma::load_matrix_sync(fbl, sW1l + kt * 16 * W1S + j * 16, W1S);
                    wmma::mma_sync(acc, fah[kt], fbh, acc);
                    wmma::mma_sync(acc, fah[kt], fbl, acc);
                    wmma::mma_sync(acc, fal[kt], fbh, acc);
                }
                wmma::store_matrix_sync(Cb + j * 16, acc, CS, wmma::mem_row_major);
            }
        }
        __syncwarp();
        gelu_split_epilogue(Cb, aHi, aLo, lane);
        __syncwarp();

        // ---- projections + run-aggregated scatter, two 64-col passes ------------
        FragA fah[4], fal[4];
        #pragma unroll
        for (int kt = 0; kt < 4; kt++) {
            wmma::load_matrix_sync(fah[kt], aHi + kt * 16, AS);
            wmma::load_matrix_sync(fal[kt], aLo + kt * 16, AS);
        }

        #pragma unroll
        for (int pass = 0; pass < 2; pass++) {
            #pragma unroll
            for (int j = 0; j < 4; j++) {
                FragC acc;
                wmma::fill_fragment(acc, 0.0f);
                int ncol = pass * 64 + j * 16;
                #pragma unroll
                for (int kt = 0; kt < 4; kt++) {
                    FragB fbh, fbl;
                    wmma::load_matrix_sync(fbh, sWPh + kt * 16 * WPS + ncol, WPS);
                    wmma::load_matrix_sync(fbl, sWPl + kt * 16 * WPS + ncol, WPS);
                    wmma::mma_sync(acc, fah[kt], fbh, acc);
                    wmma::mma_sync(acc, fah[kt], fbl, acc);
                    wmma::mma_sync(acc, fal[kt], fbh, acc);
                }
                wmma::store_matrix_sync(Cb + j * 16, acc, CS, wmma::mem_row_major);
            }
            __syncwarp();

            if (pass == 0) {
                // cols 0-31 = w0 term (-> n0 lo), cols 32-63 = w1 term (-> n1 lo)
                int cur = mdst[0];
                float a0 = 0.f, ax = 0.f, ay = 0.f, az = 0.f;
                #pragma unroll 4
                for (int e = 0; e < 16; e++) {
                    int d = mdst[e];
                    if (d != cur) {
                        atomicAdd(g_n0 + cur * 64 + lane, a0);
                        float* p = g_n1 + cur * 192 + lane;
                        atomicAdd(p,       ax);
                        atomicAdd(p + 64,  ay);
                        atomicAdd(p + 128, az);
                        a0 = ax = ay = az = 0.f;
                        cur = d;
                    }
                    const float* row = Cb + e * CS;
                    float v0 = row[lane];
                    float v1 = row[32 + lane];
                    float e0 = g_f0[msrc[e] * 32 + lane];
                    a0 += v0 * e0 * msh0[e];
                    float tv = v1 * e0;
                    ax += tv * msh1[e * 3 + 0];
                    ay += tv * msh1[e * 3 + 1];
                    az += tv * msh1[e * 3 + 2];
                }
                atomicAdd(g_n0 + cur * 64 + lane, a0);
                float* p = g_n1 + cur * 192 + lane;
                atomicAdd(p,       ax);
                atomicAdd(p + 64,  ay);
                atomicAdd(p + 128, az);
            } else {
                // cols 0-31 = w2 term (-> n1 hi), cols 32-63 = w3 term (-> n0 hi)
                int cur = mdst[0];
                float b3 = 0.f, bx = 0.f, by = 0.f, bz = 0.f;
                #pragma unroll 4
                for (int e = 0; e < 16; e++) {
                    int d = mdst[e];
                    if (d != cur) {
                        atomicAdd(g_n0 + cur * 64 + 32 + lane, b3);
                        float* p = g_n1 + cur * 192 + 32 + lane;
                        atomicAdd(p,       bx);
                        atomicAdd(p + 64,  by);
                        atomicAdd(p + 128, bz);
                        b3 = bx = by = bz = 0.f;
                        cur = d;
                    }
                    const float* row = Cb + e * CS;
                    float v2 = row[lane];
                    float v3 = row[32 + lane];
                    const float* f1 = g_f1 + msrc[e] * 96 + lane;
                    float fx = f1[0], fy = f1[32], fz = f1[64];
                    float t2 = v2 * msh0[e];
                    bx += t2 * fx;
                    by += t2 * fy;
                    bz += t2 * fz;
                    float dsum = fx * msh1[e * 3 + 0] + fy * msh1[e * 3 + 1]
                               + fz * msh1[e * 3 + 2];
                    b3 += v3 * dsum;   // inv_sqrt3 folded into wp3 weights
                }
                atomicAdd(g_n0 + cur * 64 + 32 + lane, b3);
                float* p = g_n1 + cur * 192 + 32 + lane;
                atomicAdd(p,       bx);
                atomicAdd(p + 64,  by);
                atomicAdd(p + 128, bz);
            }
            __syncwarp();
        }
    }
}

// ---------------- kernel 3: output transform ---------------------------------
#define OUT_WARPS 8
#define OUT_SMEM_BYTES ((2048 + 2048) * 4 + OUT_WARPS * 1024 * 4)

__global__ __launch_bounds__(OUT_WARPS * 32, 2)
void out_kernel(const float* __restrict__ Wout0,
                const float* __restrict__ Wout1,
                float* __restrict__ out) {
    extern __shared__ float smf[];
    float2* sW0t = (float2*)smf;
    float2* sW1t = (float2*)(smf + 2048);
    float*  sStg = smf + 4096;

    const float osc = MIX_S * INV_SQRT_2MUL;
    for (int i = threadIdx.x; i < 1024; i += blockDim.x) {
        int kp = i >> 5, c = i & 31;
        sW0t[i] = make_float2(Wout0[(2 * kp) * 32 + c] * osc,
                              Wout0[(2 * kp + 1) * 32 + c] * osc);
        sW1t[i] = make_float2(Wout1[(2 * kp) * 32 + c] * osc,
                              Wout1[(2 * kp + 1) * 32 + c] * osc);
    }
    __syncthreads();

    const int lane = threadIdx.x & 31;
    const int warp = threadIdx.x >> 5;
    float* stg = sStg + warp * 1024;

    int gw = blockIdx.x * OUT_WARPS + warp;
    int nw = gridDim.x * OUT_WARPS;
    const int NG = N_NODES / 4;

    for (int g = gw; g < NG; g += nw) {
        const int nb = g * 4;

        #pragma unroll
        for (int m = 0; m < 4; m++) {
            const float* n0s = g_n0 + (nb + m) * 64;
            const float* n1s = g_n1 + (nb + m) * 192;
            float* s = stg + m * 256;
            s[lane]      = n0s[lane];
            s[32 + lane] = n0s[32 + lane];
            #pragma unroll
            for (int i = 0; i < 3; i++) {
                s[64 + i * 64 + lane]      = n1s[i * 64 + lane];
                s[64 + i * 64 + 32 + lane] = n1s[i * 64 + 32 + lane];
            }
        }
        __syncwarp();

        u64 accS[4];
        #pragma unroll
        for (int m = 0; m < 4; m++)
            accS[m] = pack2(g_self0[(nb + m) * 32 + lane], 0.0f);
        #pragma unroll 8
        for (int kp = 0; kp < 32; kp++) {
            u64 w2 = ld2(sW0t + kp * 32 + lane);
            #pragma unroll
            for (int m = 0; m < 4; m++) {
                u64 h2 = ld2((const float2*)(stg + m * 256 + 2 * kp));
                accS[m] = fma2(w2, h2, accS[m]);
            }
        }
        #pragma unroll
        for (int m = 0; m < 4; m++) {
            float2 tt = unpack2(accS[m]);
            out[(nb + m) * 128 + lane] = tt.x + tt.y;
        }

        u64 accV[4][3];
        #pragma unroll
        for (int m = 0; m < 4; m++)
            #pragma unroll
            for (int i = 0; i < 3; i++)
                accV[m][i] = pack2(g_self1[(nb + m) * 96 + i * 32 + lane], 0.0f);
        #pragma unroll 4
        for (int kp = 0; kp < 32; kp++) {
            u64 w2 = ld2(sW1t + kp * 32 + lane);
            #pragma unroll
            for (int m = 0; m < 4; m++) {
                const float* s = stg + m * 256 + 64;
                u64 h0 = ld2((const float2*)(s + 0 * 64 + 2 * kp));
                u64 h1 = ld2((const float2*)(s + 1 * 64 + 2 * kp));
                u64 h2v = ld2((const float2*)(s + 2 * 64 + 2 * kp));
                accV[m][0] = fma2(w2, h0, accV[m][0]);
                accV[m][1] = fma2(w2, h1, accV[m][1]);
                accV[m][2] = fma2(w2, h2v, accV[m][2]);
            }
        }
        #pragma unroll
        for (int m = 0; m < 4; m++) {
            #pragma unroll
            for (int i = 0; i < 3; i++) {
                float2 tt = unpack2(accV[m][i]);
                out[(nb + m) * 128 + 32 + lane * 3 + i] = tt.x + tt.y;
            }
        }
    }
}

// ---------------- launch -------------------------------------------------------
extern "C" void kernel_launch(void* const* d_in, const int* in_sizes, int n_in,
                              void* d_out, int out_size) {
    const float* node_s      = (const float*)d_in[0];
    const float* node_v      = (const float*)d_in[1];
    const float* sh0         = (const float*)d_in[2];
    const float* sh1         = (const float*)d_in[3];
    const float* edge_scalar = (const float*)d_in[4];
    const int*   edge_src    = (const int*)d_in[5];
    const int*   edge_dst    = (const int*)d_in[6];
    const float* W_feat0     = (const float*)d_in[7];
    const float* W_self0     = (const float*)d_in[8];
    const float* W_feat1     = (const float*)d_in[9];
    const float* W_self1     = (const float*)d_in[10];
    const float* mlp_w0      = (const float*)d_in[11];
    const float* mlp_w1      = (const float*)d_in[12];
    const float* wp0         = (const float*)d_in[13];
    const float* wp1         = (const float*)d_in[14];
    const float* wp2         = (const float*)d_in[15];
    const float* wp3         = (const float*)d_in[16];
    const float* W_out0      = (const float*)d_in[17];
    const float* W_out1      = (const float*)d_in[18];
    float* out = (float*)d_out;

    node_pre_kernel<<<PRE_BLOCKS + ZERO_BLOCKS, 256>>>(node_s, node_v,
                                                       W_feat0, W_self0,
                                                       W_feat1, W_self1);
    hist_kernel<<<(N_EDGES + 255) / 256, 256>>>(edge_dst);
    scan_kernel<<<1, 1024>>>();
    scatter_kernel<<<(N_EDGES + 255) / 256, 256>>>(edge_dst);

    cudaFuncSetAttribute(edge_kernel,
                         cudaFuncAttributeMaxDynamicSharedMemorySize,
                         EDGE_SMEM_BYTES);
    edge_kernel<<<148, EDGE_WARPS * 32, EDGE_SMEM_BYTES>>>(
        sh0, sh1, edge_scalar, edge_src, edge_dst,
        mlp_w0, mlp_w1, wp0, wp1, wp2, wp3);

    cudaFuncSetAttribute(out_kernel,
                         cudaFuncAttributeMaxDynamicSharedMemorySize,
                         OUT_SMEM_BYTES);
    out_kernel<<<391, OUT_WARPS * 32, OUT_SMEM_BYTES>>>(W_out0, W_out1, out);
}

// round 7
// speedup vs baseline: 1.0770x; 1.0770x over previous
#include <cuda_runtime.h>
#include <math.h>

#define N_NODES 50000
#define N_EDGES 800000
#define MULC 32
#define RADC 8
#define FCC 64
#define EB 8

#define INV_SQRT_MUL 0.17677669529663687f
#define INV_SQRT_RAD 0.35355339059327373f
#define INV_SQRT_FC  0.125f
#define INV_SQRT_NN  0.25f
#define INV_SQRT_2MUL 0.125f
#define INV_SQRT3_C 0.5773502691896258f
#define MIX_C 0.9238795325112867f
#define MIX_S 0.3826834323650898f

typedef unsigned long long u64;

// ---------------- f32x2 packed-math helpers -----------------------------------
__device__ __forceinline__ u64 pack2(float lo, float hi) {
    u64 d; asm("mov.b64 %0, {%1, %2};" : "=l"(d) : "f"(lo), "f"(hi)); return d;
}
__device__ __forceinline__ float2 unpack2(u64 v) {
    float lo, hi; asm("mov.b64 {%0, %1}, %2;" : "=f"(lo), "=f"(hi) : "l"(v));
    return make_float2(lo, hi);
}
__device__ __forceinline__ u64 fma2(u64 a, u64 b, u64 c) {
    u64 d; asm("fma.rn.f32x2 %0, %1, %2, %3;" : "=l"(d) : "l"(a), "l"(b), "l"(c));
    return d;
}
__device__ __forceinline__ u64 ld2(const float2* p) {
    float2 v = *p;
    u64 d; asm("mov.b64 %0, {%1, %2};" : "=l"(d) : "f"(v.x), "f"(v.y)); return d;
}

// gelu(x) = x * sigmoid(2u),  u = 0.79788456(x + 0.044715 x^3)
__device__ __forceinline__ float gelu_fast(float x) {
    float x2 = x * x;
    float arg = x * (-1.5957691216057308f - 0.07135481627352344f * x2);
    float p = __expf(arg);
    return __fdividef(x, 1.0f + p);
}

// ---------------- scratch ------------------------------------------------------
__device__ __align__(16) float g_f0[N_NODES * MULC];
__device__ __align__(16) float g_f1[N_NODES * 3 * MULC];
__device__ __align__(16) float g_self0[N_NODES * MULC];
__device__ __align__(16) float g_self1[N_NODES * 3 * MULC];
__device__ __align__(16) float g_n0[N_NODES * 2 * MULC];
__device__ __align__(16) float g_n1[N_NODES * 3 * 2 * MULC];

// ---------------- kernel 1: node pre-transforms (f32x2) + zeroing --------------
#define PRE_BLOCKS 800
#define ZERO_BLOCKS 288
#define NPGROUPS (N_NODES / 4)   /* 12500 */

__global__ __launch_bounds__(256, 3)
void node_pre_kernel(const float* __restrict__ node_s,
                     const float* __restrict__ node_v,
                     const float* __restrict__ Wf0,
                     const float* __restrict__ Ws0,
                     const float* __restrict__ Wf1,
                     const float* __restrict__ Ws1) {
    if (blockIdx.x >= PRE_BLOCKS) {
        int i = (blockIdx.x - PRE_BLOCKS) * blockDim.x + threadIdx.x;
        int stride = ZERO_BLOCKS * blockDim.x;
        float4* p0 = (float4*)g_n0;
        float4* p1 = (float4*)g_n1;
        const float4 z = make_float4(0.f, 0.f, 0.f, 0.f);
        for (int k = i; k < N_NODES * 16; k += stride) p0[k] = z;
        for (int k = i; k < N_NODES * 48; k += stride) p1[k] = z;
        return;
    }

    // weights as k-pair float2, pre-scaled
    __shared__ float2 sWf0p[512], sWs0p[512], sWf1p[512], sWs1p[512];
    __shared__ float sStage[8][512];   // per warp: [0:128)=s rows, [128:512)=v rows transposed

    for (int i = threadIdx.x; i < 512; i += blockDim.x) {
        int kp = i >> 5, v = i & 31;
        sWf0p[i] = make_float2(Wf0[(2 * kp) * 32 + v] * INV_SQRT_MUL,
                               Wf0[(2 * kp + 1) * 32 + v] * INV_SQRT_MUL);
        sWs0p[i] = make_float2(Ws0[(2 * kp) * 32 + v] * (INV_SQRT_MUL * MIX_C),
                               Ws0[(2 * kp + 1) * 32 + v] * (INV_SQRT_MUL * MIX_C));
        sWf1p[i] = make_float2(Wf1[(2 * kp) * 32 + v] * INV_SQRT_MUL,
                               Wf1[(2 * kp + 1) * 32 + v] * INV_SQRT_MUL);
        sWs1p[i] = make_float2(Ws1[(2 * kp) * 32 + v] * (INV_SQRT_MUL * MIX_C),
                               Ws1[(2 * kp + 1) * 32 + v] * (INV_SQRT_MUL * MIX_C));
    }
    __syncthreads();

    const int lane = threadIdx.x & 31;
    const int warp = threadIdx.x >> 5;
    float* stg = sStage[warp];

    for (int g = blockIdx.x * 8 + warp; g < NPGROUPS; g += PRE_BLOCKS * 8) {
        const int nb = g * 4;

        // stage: s rows natural; v rows transposed to [i*32 + u]
        #pragma unroll
        for (int m = 0; m < 4; m++) {
            stg[m * 32 + lane] = node_s[(nb + m) * 32 + lane];
            #pragma unroll
            for (int c = 0; c < 3; c++) {
                int j = c * 32 + lane;
                float val = node_v[(nb + m) * 96 + j];
                int u = j / 3, ii = j - u * 3;
                stg[128 + m * 96 + ii * 32 + u] = val;
            }
        }
        __syncwarp();

        // scalar channel: f0, self0
        u64 af0[4], as0[4];
        #pragma unroll
        for (int m = 0; m < 4; m++) { af0[m] = pack2(0.f, 0.f); as0[m] = pack2(0.f, 0.f); }
        #pragma unroll 8
        for (int kp = 0; kp < 16; kp++) {
            u64 wf = ld2(sWf0p + kp * 32 + lane);
            u64 ws = ld2(sWs0p + kp * 32 + lane);
            #pragma unroll
            for (int m = 0; m < 4; m++) {
                u64 h2 = ld2((const float2*)(stg + m * 32 + 2 * kp));
                af0[m] = fma2(wf, h2, af0[m]);
                as0[m] = fma2(ws, h2, as0[m]);
            }
        }
        #pragma unroll
        for (int m = 0; m < 4; m++) {
            float2 a = unpack2(af0[m]);
            float2 b = unpack2(as0[m]);
            g_f0[(nb + m) * 32 + lane] = a.x + a.y;
            g_self0[(nb + m) * 32 + lane] = b.x + b.y;
        }

        // vector channels: f1, self1
        u64 af1[4][3], as1[4][3];
        #pragma unroll
        for (int m = 0; m < 4; m++)
            #pragma unroll
            for (int i = 0; i < 3; i++) { af1[m][i] = pack2(0.f, 0.f); as1[m][i] = pack2(0.f, 0.f); }
        #pragma unroll 4
        for (int kp = 0; kp < 16; kp++) {
            u64 wf = ld2(sWf1p + kp * 32 + lane);
            u64 ws = ld2(sWs1p + kp * 32 + lane);
            #pragma unroll
            for (int m = 0; m < 4; m++) {
                #pragma unroll
                for (int i = 0; i < 3; i++) {
                    u64 h2 = ld2((const float2*)(stg + 128 + m * 96 + i * 32 + 2 * kp));
                    af1[m][i] = fma2(wf, h2, af1[m][i]);
                    as1[m][i] = fma2(ws, h2, as1[m][i]);
                }
            }
        }
        #pragma unroll
        for (int m = 0; m < 4; m++) {
            #pragma unroll
            for (int i = 0; i < 3; i++) {
                float2 a = unpack2(af1[m][i]);
                float2 b = unpack2(as1[m][i]);
                g_f1[(nb + m) * 96 + i * 32 + lane] = a.x + a.y;
                g_self1[(nb + m) * 96 + i * 32 + lane] = b.x + b.y;
            }
        }
        __syncwarp();
    }
}

// ---------------- kernel 2: edge phase (f32x2, EB=8, occ 3, 5 launch parts) ---
#define EDGE_WARPS 8
#define EDGE_GRID 444
#define NPARTS 5
#define NB_TOTAL (N_EDGES / EB)        /* 100000 */
#define NB_PART (NB_TOTAL / NPARTS)    /* 20000 */

// smem floats: sW0 512 | sW1p 4096 | sWP01 4096 | sWP23 4096 | sH 4096
#define EDGE_SMEM_BYTES ((512 + 4096 + 4096 + 4096 + 4096) * 4)   /* 67.6 KB */

__global__ __launch_bounds__(EDGE_WARPS * 32, 3)
void edge_kernel(int part,
                 const float* __restrict__ sh0,
                 const float* __restrict__ sh1,
                 const float* __restrict__ edge_scalar,
                 const int* __restrict__ edge_src,
                 const int* __restrict__ edge_dst,
                 const float* __restrict__ mlp_w0,
                 const float* __restrict__ mlp_w1,
                 const float* __restrict__ wp0,
                 const float* __restrict__ wp1,
                 const float* __restrict__ wp2,
                 const float* __restrict__ wp3) {
    extern __shared__ float sm[];
    float*  sW0   = sm;                          // 8*64
    float2* sW1p  = (float2*)(sm + 512);         // [k][c] -> (W1[k][c], W1[k][c+32])
    float2* sWP01 = (float2*)(sm + 4608);        // [k][c] -> (wp0, wp1)
    float2* sWP23 = (float2*)(sm + 8704);        // [k][c] -> (wp2, wp3)
    float2* sH    = (float2*)(sm + 12800);       // per-warp 4 pairs * 64

    for (int i = threadIdx.x; i < RADC * FCC; i += blockDim.x)
        sW0[i] = mlp_w0[i] * INV_SQRT_RAD;
    for (int i = threadIdx.x; i < 2048; i += blockDim.x) {
        int k = i >> 5, c = i & 31;
        sW1p[i] = make_float2(mlp_w1[k * 64 + c] * INV_SQRT_FC,
                              mlp_w1[k * 64 + 32 + c] * INV_SQRT_FC);
    }
    const float wpsc = INV_SQRT_FC * INV_SQRT_NN;
    for (int i = threadIdx.x; i < FCC * MULC; i += blockDim.x) {
        sWP01[i] = make_float2(wp0[i] * wpsc, wp1[i] * wpsc);
        sWP23[i] = make_float2(wp2[i] * wpsc, wp3[i] * wpsc);
    }
    __syncthreads();

    const int lane = threadIdx.x & 31;
    const int warp = threadIdx.x >> 5;
    float2* hp = sH + warp * 256;

    int gw = blockIdx.x * EDGE_WARPS + warp;
    const int b_lo = part * NB_PART;
    const int b_hi = b_lo + NB_PART;

    for (int b = b_lo + gw; b < b_hi; b += EDGE_GRID * EDGE_WARPS) {
        const int eb = b * EB;

        float esA = edge_scalar[eb * 8 + lane];
        float esB = edge_scalar[eb * 8 + 32 + lane];
        int srcv = 0, dstv = 0; float sh0v = 0.f, sh1v = 0.f;
        if (lane < 8) {
            srcv = edge_src[eb + lane];
            dstv = edge_dst[eb + lane];
            sh0v = sh0[eb + lane];
        }
        if (lane < 24) sh1v = sh1[eb * 3 + lane];

        // ---- layer 0: 8 -> 64 -------------------------------------------------
        u64 aL[4] = {0ull, 0ull, 0ull, 0ull};
        u64 aH[4] = {0ull, 0ull, 0ull, 0ull};
        #pragma unroll
        for (int r = 0; r < 8; r++) {
            float wl = sW0[r * 64 + lane];
            float wh = sW0[r * 64 + 32 + lane];
            u64 wl2 = pack2(wl, wl), wh2 = pack2(wh, wh);
            float t0 = __shfl_sync(0xffffffffu, esA, r);
            float t1 = __shfl_sync(0xffffffffu, esA, 8 + r);
            float t2 = __shfl_sync(0xffffffffu, esA, 16 + r);
            float t3 = __shfl_sync(0xffffffffu, esA, 24 + r);
            float t4 = __shfl_sync(0xffffffffu, esB, r);
            float t5 = __shfl_sync(0xffffffffu, esB, 8 + r);
            float t6 = __shfl_sync(0xffffffffu, esB, 16 + r);
            float t7 = __shfl_sync(0xffffffffu, esB, 24 + r);
            u64 e01 = pack2(t0, t1), e23 = pack2(t2, t3);
            u64 e45 = pack2(t4, t5), e67 = pack2(t6, t7);
            aL[0] = fma2(wl2, e01, aL[0]);  aH[0] = fma2(wh2, e01, aH[0]);
            aL[1] = fma2(wl2, e23, aL[1]);  aH[1] = fma2(wh2, e23, aH[1]);
            aL[2] = fma2(wl2, e45, aL[2]);  aH[2] = fma2(wh2, e45, aH[2]);
            aL[3] = fma2(wl2, e67, aL[3]);  aH[3] = fma2(wh2, e67, aH[3]);
        }
        __syncwarp();
        #pragma unroll
        for (int p = 0; p < 4; p++) {
            float2 lo = unpack2(aL[p]);
            float2 hi = unpack2(aH[p]);
            hp[p * 64 + lane]      = make_float2(gelu_fast(lo.x), gelu_fast(lo.y));
            hp[p * 64 + 32 + lane] = make_float2(gelu_fast(hi.x), gelu_fast(hi.y));
        }
        __syncwarp();

        // ---- layer 1: 64 -> 64 -----------------------------------------------
        u64 bL[4] = {0ull, 0ull, 0ull, 0ull};
        u64 bH[4] = {0ull, 0ull, 0ull, 0ull};
        #pragma unroll 8
        for (int k = 0; k < 64; k++) {
            float2 w = sW1p[k * 32 + lane];
            u64 wl2 = pack2(w.x, w.x), wh2 = pack2(w.y, w.y);
            u64 h01 = ld2(hp + 0 * 64 + k);
            u64 h23 = ld2(hp + 1 * 64 + k);
            u64 h45 = ld2(hp + 2 * 64 + k);
            u64 h67 = ld2(hp + 3 * 64 + k);
            bL[0] = fma2(wl2, h01, bL[0]);  bH[0] = fma2(wh2, h01, bH[0]);
            bL[1] = fma2(wl2, h23, bL[1]);  bH[1] = fma2(wh2, h23, bH[1]);
            bL[2] = fma2(wl2, h45, bL[2]);  bH[2] = fma2(wh2, h45, bH[2]);
            bL[3] = fma2(wl2, h67, bL[3]);  bH[3] = fma2(wh2, h67, bH[3]);
        }
        __syncwarp();
        #pragma unroll
        for (int p = 0; p < 4; p++) {
            float2 lo = unpack2(bL[p]);
            float2 hi = unpack2(bH[p]);
            hp[p * 64 + lane]      = make_float2(gelu_fast(lo.x), gelu_fast(lo.y));
            hp[p * 64 + 32 + lane] = make_float2(gelu_fast(hi.x), gelu_fast(hi.y));
        }
        __syncwarp();

        // ---- projections pass A: w0, w1 ----------------------------------------
        float w0f[8], w1f[8], w2f[8], w3f[8];
        {
            u64 c0[4] = {0ull, 0ull, 0ull, 0ull};
            u64 c1[4] = {0ull, 0ull, 0ull, 0ull};
            #pragma unroll 8
            for (int k = 0; k < 64; k++) {
                float2 w = sWP01[k * 32 + lane];
                u64 w0d = pack2(w.x, w.x), w1d = pack2(w.y, w.y);
                u64 h01 = ld2(hp + 0 * 64 + k);
                u64 h23 = ld2(hp + 1 * 64 + k);
                u64 h45 = ld2(hp + 2 * 64 + k);
                u64 h67 = ld2(hp + 3 * 64 + k);
                c0[0] = fma2(w0d, h01, c0[0]);  c0[1] = fma2(w0d, h23, c0[1]);
                c0[2] = fma2(w0d, h45, c0[2]);  c0[3] = fma2(w0d, h67, c0[3]);
                c1[0] = fma2(w1d, h01, c1[0]);  c1[1] = fma2(w1d, h23, c1[1]);
                c1[2] = fma2(w1d, h45, c1[2]);  c1[3] = fma2(w1d, h67, c1[3]);
            }
            #pragma unroll
            for (int p = 0; p < 4; p++) {
                float2 t;
                t = unpack2(c0[p]); w0f[2 * p] = t.x; w0f[2 * p + 1] = t.y;
                t = unpack2(c1[p]); w1f[2 * p] = t.x; w1f[2 * p + 1] = t.y;
            }
        }
        // ---- projections pass B: w2, w3 ----------------------------------------
        {
            u64 c2[4] = {0ull, 0ull, 0ull, 0ull};
            u64 c3[4] = {0ull, 0ull, 0ull, 0ull};
            #pragma unroll 8
            for (int k = 0; k < 64; k++) {
                float2 w = sWP23[k * 32 + lane];
                u64 w2d = pack2(w.x, w.x), w3d = pack2(w.y, w.y);
                u64 h01 = ld2(hp + 0 * 64 + k);
                u64 h23 = ld2(hp + 1 * 64 + k);
                u64 h45 = ld2(hp + 2 * 64 + k);
                u64 h67 = ld2(hp + 3 * 64 + k);
                c2[0] = fma2(w2d, h01, c2[0]);  c2[1] = fma2(w2d, h23, c2[1]);
                c2[2] = fma2(w2d, h45, c2[2]);  c2[3] = fma2(w2d, h67, c2[3]);
                c3[0] = fma2(w3d, h01, c3[0]);  c3[1] = fma2(w3d, h23, c3[1]);
                c3[2] = fma2(w3d, h45, c3[2]);  c3[3] = fma2(w3d, h67, c3[3]);
            }
            #pragma unroll
            for (int p = 0; p < 4; p++) {
                float2 t;
                t = unpack2(c2[p]); w2f[2 * p] = t.x; w2f[2 * p + 1] = t.y;
                t = unpack2(c3[p]); w3f[2 * p] = t.x; w3f[2 * p + 1] = t.y;
            }
        }

        // ---- tensor products + scatter-add ------------------------------------
        #pragma unroll
        for (int j = 0; j < 8; j++) {
            int src   = __shfl_sync(0xffffffffu, srcv, j);
            int dst   = __shfl_sync(0xffffffffu, dstv, j);
            float s0  = __shfl_sync(0xffffffffu, sh0v, j);
            float shx = __shfl_sync(0xffffffffu, sh1v, 3 * j + 0);
            float shy = __shfl_sync(0xffffffffu, sh1v, 3 * j + 1);
            float shz = __shfl_sync(0xffffffffu, sh1v, 3 * j + 2);

            const float* f0p = g_f0 + src * 32;
            const float* f1p = g_f1 + src * 96;
            float e0  = f0p[lane];
            float e1x = f1p[lane];
            float e1y = f1p[32 + lane];
            float e1z = f1p[64 + lane];

            float p0 = w0f[j] * e0 * s0;
            float d  = e1x * shx + e1y * shy + e1z * shz;
            float p3 = w3f[j] * d * INV_SQRT3_C;
            float w1e0 = w1f[j] * e0;
            float w2s0 = w2f[j] * s0;

            float* n0p = g_n0 + dst * 64;
            float* n1p = g_n1 + dst * 192;
            atomicAdd(n0p + lane,      p0);
            atomicAdd(n0p + 32 + lane, p3);
            atomicAdd(n1p + 0 * 64 + lane,      w1e0 * shx);
            atomicAdd(n1p + 0 * 64 + 32 + lane, w2s0 * e1x);
            atomicAdd(n1p + 1 * 64 + lane,      w1e0 * shy);
            atomicAdd(n1p + 1 * 64 + 32 + lane, w2s0 * e1y);
            atomicAdd(n1p + 2 * 64 + lane,      w1e0 * shz);
            atomicAdd(n1p + 2 * 64 + 32 + lane, w2s0 * e1z);
        }
    }
}

// ---------------- kernel 3: output transform -----------------------------------
#define OUT_WARPS 8
#define OUT_SMEM_BYTES ((2048 + 2048) * 4 + OUT_WARPS * 1024 * 4)

__global__ __launch_bounds__(OUT_WARPS * 32, 2)
void out_kernel(const float* __restrict__ Wout0,
                const float* __restrict__ Wout1,
                float* __restrict__ out) {
    extern __shared__ float smf[];
    float2* sW0t = (float2*)smf;
    float2* sW1t = (float2*)(smf + 2048);
    float*  sStg = smf + 4096;

    const float osc = MIX_S * INV_SQRT_2MUL;
    for (int i = threadIdx.x; i < 1024; i += blockDim.x) {
        int kp = i >> 5, c = i & 31;
        sW0t[i] = make_float2(Wout0[(2 * kp) * 32 + c] * osc,
                              Wout0[(2 * kp + 1) * 32 + c] * osc);
        sW1t[i] = make_float2(Wout1[(2 * kp) * 32 + c] * osc,
                              Wout1[(2 * kp + 1) * 32 + c] * osc);
    }
    __syncthreads();

    const int lane = threadIdx.x & 31;
    const int warp = threadIdx.x >> 5;
    float* stg = sStg + warp * 1024;

    int gw = blockIdx.x * OUT_WARPS + warp;
    int nw = gridDim.x * OUT_WARPS;
    const int NG = N_NODES / 4;

    for (int g = gw; g < NG; g += nw) {
        const int nb = g * 4;

        #pragma unroll
        for (int m = 0; m < 4; m++) {
            const float* n0s = g_n0 + (nb + m) * 64;
            const float* n1s = g_n1 + (nb + m) * 192;
            float* s = stg + m * 256;
            s[lane]      = n0s[lane];
            s[32 + lane] = n0s[32 + lane];
            #pragma unroll
            for (int i = 0; i < 3; i++) {
                s[64 + i * 64 + lane]      = n1s[i * 64 + lane];
                s[64 + i * 64 + 32 + lane] = n1s[i * 64 + 32 + lane];
            }
        }
        __syncwarp();

        u64 accS[4];
        #pragma unroll
        for (int m = 0; m < 4; m++)
            accS[m] = pack2(g_self0[(nb + m) * 32 + lane], 0.0f);
        #pragma unroll 8
        for (int kp = 0; kp < 32; kp++) {
            u64 w2 = ld2(sW0t + kp * 32 + lane);
            #pragma unroll
            for (int m = 0; m < 4; m++) {
                u64 h2 = ld2((const float2*)(stg + m * 256 + 2 * kp));
                accS[m] = fma2(w2, h2, accS[m]);
            }
        }
        #pragma unroll
        for (int m = 0; m < 4; m++) {
            float2 tt = unpack2(accS[m]);
            out[(nb + m) * 128 + lane] = tt.x + tt.y;
        }

        u64 accV[4][3];
        #pragma unroll
        for (int m = 0; m < 4; m++)
            #pragma unroll
            for (int i = 0; i < 3; i++)
                accV[m][i] = pack2(g_self1[(nb + m) * 96 + i * 32 + lane], 0.0f);
        #pragma unroll 4
        for (int kp = 0; kp < 32; kp++) {
            u64 w2 = ld2(sW1t + kp * 32 + lane);
            #pragma unroll
            for (int m = 0; m < 4; m++) {
                const float* s = stg + m * 256 + 64;
                u64 h0 = ld2((const float2*)(s + 0 * 64 + 2 * kp));
                u64 h1 = ld2((const float2*)(s + 1 * 64 + 2 * kp));
                u64 h2v = ld2((const float2*)(s + 2 * 64 + 2 * kp));
                accV[m][0] = fma2(w2, h0, accV[m][0]);
                accV[m][1] = fma2(w2, h1, accV[m][1]);
                accV[m][2] = fma2(w2, h2v, accV[m][2]);
            }
        }
        #pragma unroll
        for (int m = 0; m < 4; m++) {
            #pragma unroll
            for (int i = 0; i < 3; i++) {
                float2 tt = unpack2(accV[m][i]);
                out[(nb + m) * 128 + 32 + lane * 3 + i] = tt.x + tt.y;
            }
        }
    }
}

// ---------------- launch ---------------------------------------------------------
extern "C" void kernel_launch(void* const* d_in, const int* in_sizes, int n_in,
                              void* d_out, int out_size) {
    const float* node_s      = (const float*)d_in[0];
    const float* node_v      = (const float*)d_in[1];
    const float* sh0         = (const float*)d_in[2];
    const float* sh1         = (const float*)d_in[3];
    const float* edge_scalar = (const float*)d_in[4];
    const int*   edge_src    = (const int*)d_in[5];
    const int*   edge_dst    = (const int*)d_in[6];
    const float* W_feat0     = (const float*)d_in[7];
    const float* W_self0     = (const float*)d_in[8];
    const float* W_feat1     = (const float*)d_in[9];
    const float* W_self1     = (const float*)d_in[10];
    const float* mlp_w0      = (const float*)d_in[11];
    const float* mlp_w1      = (const float*)d_in[12];
    const float* wp0         = (const float*)d_in[13];
    const float* wp1         = (const float*)d_in[14];
    const float* wp2         = (const float*)d_in[15];
    const float* wp3         = (const float*)d_in[16];
    const float* W_out0      = (const float*)d_in[17];
    const float* W_out1      = (const float*)d_in[18];
    float* out = (float*)d_out;

    node_pre_kernel<<<PRE_BLOCKS + ZERO_BLOCKS, 256>>>(node_s, node_v,
                                                       W_feat0, W_self0,
                                                       W_feat1, W_self1);

    cudaFuncSetAttribute(edge_kernel,
                         cudaFuncAttributeMaxDynamicSharedMemorySize,
                         EDGE_SMEM_BYTES);
    for (int part = 0; part < NPARTS; part++) {
        edge_kernel<<<EDGE_GRID, EDGE_WARPS * 32, EDGE_SMEM_BYTES>>>(
            part, sh0, sh1, edge_scalar, edge_src, edge_dst,
            mlp_w0, mlp_w1, wp0, wp1, wp2, wp3);
    }

    cudaFuncSetAttribute(out_kernel,
                         cudaFuncAttributeMaxDynamicSharedMemorySize,
                         OUT_SMEM_BYTES);
    out_kernel<<<391, OUT_WARPS * 32, OUT_SMEM_BYTES>>>(W_out0, W_out1, out);
}